// round 1
// baseline (speedup 1.0000x reference)
#include <cuda_runtime.h>

#define BATCH 8
#define NSEQ  1024
#define DIM   512
#define NH    8
#define DH    64
#define BH    (BATCH*NH)
#define SCALE 0.044194173824159216f   // 512^-0.5

// ---------------- scratch (device globals: alloc-guard safe) ----------------
__device__ float g_q1[BH*NSEQ*DH];
__device__ float g_k1[BH*NSEQ*DH];
__device__ float g_v1[BH*NSEQ*DH];
__device__ float g_o1[BATCH*NSEQ*DIM];
__device__ float g_q2[BH*NSEQ*DH];
__device__ float g_k2[BH*NSEQ*DH];
__device__ float g_v2[BH*NSEQ*DH];
__device__ float g_att[BATCH*NSEQ*DIM];

// ---------------- GEMM: C[M,Nc] = A[M,K] @ W[K,Nc] + bias ----------------
// qkv_mode=1: scatter columns into q/k/v [B,H,N,D] buffers.
__global__ __launch_bounds__(256) void gemm_kernel(
    const float* __restrict__ A, const float* __restrict__ W,
    const float* __restrict__ bias,
    float* __restrict__ C,
    float* __restrict__ Qo, float* __restrict__ Ko, float* __restrict__ Vo,
    int M, int Ncols, int Kdim, int qkv_mode)
{
    __shared__ float As[64][17];   // [m][k], padded: conflict-light
    __shared__ float Bs[16][64];   // [k][n]

    const int tid = threadIdx.x;
    const int tx = tid & 15, ty = tid >> 4;
    const int row0 = blockIdx.y * 64;
    const int col0 = blockIdx.x * 64;

    const int la_m = tid >> 4, la_k = tid & 15;   // A loader
    const int lb_n = tid & 63, lb_k = tid >> 6;   // B loader

    float acc[4][4] = {};

    for (int kt = 0; kt < Kdim; kt += 16) {
        #pragma unroll
        for (int it = 0; it < 4; it++)
            As[la_m + 16*it][la_k] = A[(row0 + la_m + 16*it)*Kdim + kt + la_k];
        #pragma unroll
        for (int it = 0; it < 4; it++)
            Bs[lb_k + 4*it][lb_n] = W[(kt + lb_k + 4*it)*Ncols + col0 + lb_n];
        __syncthreads();

        #pragma unroll
        for (int kk = 0; kk < 16; kk++) {
            float a0 = As[ty*4+0][kk], a1 = As[ty*4+1][kk];
            float a2 = As[ty*4+2][kk], a3 = As[ty*4+3][kk];
            float4 bv = *(const float4*)&Bs[kk][tx*4];
            float b_[4] = {bv.x, bv.y, bv.z, bv.w};
            float a_[4] = {a0, a1, a2, a3};
            #pragma unroll
            for (int i = 0; i < 4; i++)
                #pragma unroll
                for (int j = 0; j < 4; j++)
                    acc[i][j] = fmaf(a_[i], b_[j], acc[i][j]);
        }
        __syncthreads();
    }

    #pragma unroll
    for (int i = 0; i < 4; i++) {
        const int r = row0 + ty*4 + i;
        #pragma unroll
        for (int j = 0; j < 4; j++) {
            const int c = col0 + tx*4 + j;
            const float v = acc[i][j] + bias[c];
            if (qkv_mode) {
                const int part = c >> 9;          // 0:q 1:k 2:v
                const int h    = (c >> 6) & 7;
                const int dd   = c & 63;
                const int b    = r >> 10;
                const int n    = r & 1023;
                float* dst = (part == 0) ? Qo : (part == 1) ? Ko : Vo;
                dst[(((b*NH + h)*NSEQ) + n)*DH + dd] = v;
            } else {
                C[r*Ncols + c] = v;
            }
        }
    }
}

// ---------------- attention: 1 thread = 1 query row ----------------
// STAGE1: out_i = sum_j sigmoid(s_ij * mask_ij) * v_j      (no normalization)
// STAGE2: out_i = softmax_j(s_ij * SCALE) @ v               (online softmax)
template<bool STAGE1>
__global__ __launch_bounds__(128) void attn_kernel(
    const float* __restrict__ Q, const float* __restrict__ K,
    const float* __restrict__ V, const float* __restrict__ mask,
    float* __restrict__ out)
{
    __shared__ float Ks[64][64];
    __shared__ float Vs[64][64];

    const int bh = blockIdx.x;              // 0..63
    const int b = bh >> 3, h = bh & 7;
    const int i = blockIdx.y * 128 + threadIdx.x;   // query row 0..1023

    const float* qrow = Q + (bh*NSEQ + i)*DH;
    float q[DH];
    #pragma unroll
    for (int d = 0; d < DH; d += 4) {
        float4 t = *(const float4*)(qrow + d);
        q[d] = t.x; q[d+1] = t.y; q[d+2] = t.z; q[d+3] = t.w;
    }

    float o[DH];
    #pragma unroll
    for (int d = 0; d < DH; d++) o[d] = 0.f;
    float mrun = -1e30f, lrun = 0.f;

    const float* maskrow = STAGE1 ? (mask + i*NSEQ) : nullptr;
    const float4* Ksrc = (const float4*)(K + bh*NSEQ*DH);
    const float4* Vsrc = (const float4*)(V + bh*NSEQ*DH);

    for (int kt = 0; kt < NSEQ/64; kt++) {
        __syncthreads();
        #pragma unroll
        for (int s = 0; s < 8; s++) {
            const int idx = threadIdx.x + 128*s;
            ((float4*)Ks)[idx] = Ksrc[kt*1024 + idx];
            ((float4*)Vs)[idx] = Vsrc[kt*1024 + idx];
        }
        __syncthreads();

        #pragma unroll 2
        for (int j4 = 0; j4 < 64; j4 += 4) {
            float4 mv;
            if (STAGE1) mv = *(const float4*)(maskrow + kt*64 + j4);
            const float mvals[4] = { STAGE1 ? mv.x : 0.f, STAGE1 ? mv.y : 0.f,
                                     STAGE1 ? mv.z : 0.f, STAGE1 ? mv.w : 0.f };
            #pragma unroll
            for (int u = 0; u < 4; u++) {
                const int j = j4 + u;
                float s0 = 0.f, s1 = 0.f, s2 = 0.f, s3 = 0.f;
                #pragma unroll
                for (int d = 0; d < DH; d += 4) {
                    float4 kv = *(const float4*)&Ks[j][d];
                    s0 = fmaf(q[d],   kv.x, s0);
                    s1 = fmaf(q[d+1], kv.y, s1);
                    s2 = fmaf(q[d+2], kv.z, s2);
                    s3 = fmaf(q[d+3], kv.w, s3);
                }
                float sc = (s0 + s1) + (s2 + s3);

                float p;
                if (STAGE1) {
                    p = 1.f / (1.f + __expf(-sc * mvals[u]));
                } else {
                    sc *= SCALE;
                    if (sc > mrun) {
                        const float alpha = __expf(mrun - sc);
                        lrun *= alpha;
                        #pragma unroll
                        for (int d = 0; d < DH; d++) o[d] *= alpha;
                        mrun = sc;
                    }
                    p = __expf(sc - mrun);
                    lrun += p;
                }
                #pragma unroll
                for (int d = 0; d < DH; d += 4) {
                    float4 vv = *(const float4*)&Vs[j][d];
                    o[d]   = fmaf(p, vv.x, o[d]);
                    o[d+1] = fmaf(p, vv.y, o[d+1]);
                    o[d+2] = fmaf(p, vv.z, o[d+2]);
                    o[d+3] = fmaf(p, vv.w, o[d+3]);
                }
            }
        }
    }

    const float inv = STAGE1 ? 1.f : (1.f / lrun);
    float* orow = out + (b*NSEQ + i)*DIM + h*DH;
    #pragma unroll
    for (int d = 0; d < DH; d += 4) {
        float4 t = make_float4(o[d]*inv, o[d+1]*inv, o[d+2]*inv, o[d+3]*inv);
        *(float4*)(orow + d) = t;
    }
}

// ---------------- launch ----------------
extern "C" void kernel_launch(void* const* d_in, const int* in_sizes, int n_in,
                              void* d_out, int out_size)
{
    const float* x     = (const float*)d_in[0];
    const float* mask  = (const float*)d_in[1];
    const float* Wqkv1 = (const float*)d_in[2];
    const float* bqkv1 = (const float*)d_in[3];
    const float* Wqkv2 = (const float*)d_in[4];
    const float* bqkv2 = (const float*)d_in[5];
    const float* Wnn1  = (const float*)d_in[6];
    const float* bnn1  = (const float*)d_in[7];
    float* out = (float*)d_out;

    float *q1, *k1, *v1, *o1, *q2, *k2, *v2, *att;
    cudaGetSymbolAddress((void**)&q1, g_q1);
    cudaGetSymbolAddress((void**)&k1, g_k1);
    cudaGetSymbolAddress((void**)&v1, g_v1);
    cudaGetSymbolAddress((void**)&o1, g_o1);
    cudaGetSymbolAddress((void**)&q2, g_q2);
    cudaGetSymbolAddress((void**)&k2, g_k2);
    cudaGetSymbolAddress((void**)&v2, g_v2);
    cudaGetSymbolAddress((void**)&att, g_att);

    const int M = BATCH * NSEQ;           // 8192

    dim3 gridQKV(3*DIM/64, M/64);         // 24 x 128
    dim3 gridOut(DIM/64, M/64);           // 8 x 128
    dim3 gridAtt(BH, NSEQ/128);           // 64 x 8

    // Stage 1 projection -> q1,k1,v1 [B,H,N,D]
    gemm_kernel<<<gridQKV, 256>>>(x, Wqkv1, bqkv1, nullptr, q1, k1, v1,
                                  M, 3*DIM, DIM, 1);
    // Stage 1 sigmoid attention -> o1 [B,N,DIM]
    attn_kernel<true><<<gridAtt, 128>>>(q1, k1, v1, mask, o1);
    // Stage 2 projection -> q2,k2,v2
    gemm_kernel<<<gridQKV, 256>>>(o1, Wqkv2, bqkv2, nullptr, q2, k2, v2,
                                  M, 3*DIM, DIM, 1);
    // Stage 2 softmax attention -> att [B,N,DIM]
    attn_kernel<false><<<gridAtt, 128>>>(q2, k2, v2, nullptr, att);
    // Output projection -> d_out
    gemm_kernel<<<gridOut, 256>>>(att, Wnn1, bnn1, out,
                                  nullptr, nullptr, nullptr, M, DIM, DIM, 0);
}

// round 2
// speedup vs baseline: 2.9683x; 2.9683x over previous
#include <cuda_runtime.h>
#include <cstdint>

#define BATCH 8
#define NSEQ  1024
#define DIM   512
#define NH    8
#define DH    64
#define BH    64
#define SCALE 0.044194173824159216f   // 512^-0.5

// ---------------- scratch (device globals: alloc-guard safe) ----------------
__device__ float g_q1[BH*NSEQ*DH];
__device__ float g_k1[BH*NSEQ*DH];
__device__ float g_v1[BH*NSEQ*DH];
__device__ float g_o1[BATCH*NSEQ*DIM];
__device__ float g_q2[BH*NSEQ*DH];
__device__ float g_k2[BH*NSEQ*DH];
__device__ float g_v2[BH*NSEQ*DH];
__device__ float g_att[BATCH*NSEQ*DIM];

// ---------------- tf32 helpers ----------------
__device__ __forceinline__ uint32_t f2tf(float x) {
    uint32_t r;
    asm("cvt.rna.tf32.f32 %0, %1;" : "=r"(r) : "f"(x));
    return r;
}

// D += A(m16k8,row) @ B(k8n8,col); fp32 accumulate
__device__ __forceinline__ void mma8(float* c, const uint32_t* a, const uint32_t* b) {
    asm volatile(
        "mma.sync.aligned.m16n8k8.row.col.f32.tf32.tf32.f32 "
        "{%0,%1,%2,%3}, {%4,%5,%6,%7}, {%8,%9}, {%0,%1,%2,%3};\n"
        : "+f"(c[0]), "+f"(c[1]), "+f"(c[2]), "+f"(c[3])
        : "r"(a[0]), "r"(a[1]), "r"(a[2]), "r"(a[3]), "r"(b[0]), "r"(b[1]));
}

// ---------------- GEMM: C[M,Nc] = A[M,512] @ W[512,Nc] + bias ----------------
// Block tile 128x128, 8 warps (4m x 2n), warp tile 32x64, K chunk 32.
// QKV=1: scatter columns into q/k/v [B,H,N,D] buffers.
template<int QKV>
__global__ __launch_bounds__(256) void gemm_tf32(
    const float* __restrict__ A, const float* __restrict__ W,
    const float* __restrict__ bias, float* __restrict__ C,
    float* __restrict__ Qo, float* __restrict__ Ko, float* __restrict__ Vo,
    int Ncols)
{
    __shared__ uint32_t As[128][36];   // [m][k] pad 36: frag bank = lane (CF)
    __shared__ uint32_t Bs[32][136];   // [k][n] pad 136: 8k+n distinct (CF)

    const int tid  = threadIdx.x;
    const int warp = tid >> 5, lane = tid & 31;
    const int wm = warp & 3, wn = warp >> 2;
    const int lr = lane >> 2, lc = lane & 3;
    const int row0 = blockIdx.y * 128, col0 = blockIdx.x * 128;

    const int ar = tid >> 3, ac = (tid & 7) * 4;     // A loader: 32 rows/pass x4
    const int br = tid >> 5, bc = (tid & 31) * 4;    // B loader: 8 k-rows/pass x4

    float acc[2][8][4];
    #pragma unroll
    for (int mt = 0; mt < 2; mt++)
        #pragma unroll
        for (int nt = 0; nt < 8; nt++)
            #pragma unroll
            for (int u = 0; u < 4; u++) acc[mt][nt][u] = 0.f;

    for (int kt = 0; kt < DIM; kt += 32) {
        __syncthreads();
        #pragma unroll
        for (int p = 0; p < 4; p++) {
            float4 va = *(const float4*)&A[(row0 + ar + 32*p)*DIM + kt + ac];
            uint4 ua = make_uint4(f2tf(va.x), f2tf(va.y), f2tf(va.z), f2tf(va.w));
            *(uint4*)&As[ar + 32*p][ac] = ua;
            float4 vb = *(const float4*)&W[(kt + br + 8*p)*Ncols + col0 + bc];
            uint4 ub = make_uint4(f2tf(vb.x), f2tf(vb.y), f2tf(vb.z), f2tf(vb.w));
            *(uint4*)&Bs[br + 8*p][bc] = ub;
        }
        __syncthreads();

        #pragma unroll
        for (int ks = 0; ks < 4; ks++) {
            const int k0 = ks*8 + lc;
            uint32_t af[2][4], bf[8][2];
            #pragma unroll
            for (int mt = 0; mt < 2; mt++) {
                const int r = wm*32 + mt*16 + lr;
                af[mt][0] = As[r][k0];     af[mt][1] = As[r+8][k0];
                af[mt][2] = As[r][k0+4];   af[mt][3] = As[r+8][k0+4];
            }
            #pragma unroll
            for (int nt = 0; nt < 8; nt++) {
                const int n = wn*64 + nt*8 + lr;
                bf[nt][0] = Bs[k0][n];
                bf[nt][1] = Bs[k0+4][n];
            }
            #pragma unroll
            for (int mt = 0; mt < 2; mt++)
                #pragma unroll
                for (int nt = 0; nt < 8; nt++)
                    mma8(acc[mt][nt], af[mt], bf[nt]);
        }
    }

    // epilogue
    #pragma unroll
    for (int mt = 0; mt < 2; mt++) {
        const int rbase = row0 + wm*32 + mt*16 + lr;
        #pragma unroll
        for (int nt = 0; nt < 8; nt++) {
            const int cc = col0 + wn*64 + nt*8 + 2*lc;
            const float b0 = bias[cc], b1 = bias[cc+1];
            #pragma unroll
            for (int h2 = 0; h2 < 2; h2++) {
                const int r = rbase + h2*8;
                float2 v = make_float2(acc[mt][nt][h2*2] + b0,
                                       acc[mt][nt][h2*2+1] + b1);
                if (QKV) {
                    const int part = cc >> 9;
                    const int hh   = (cc >> 6) & 7;
                    const int dd   = cc & 63;
                    const int bb   = r >> 10;
                    const int nn   = r & 1023;
                    float* dst = (part == 0) ? Qo : (part == 1) ? Ko : Vo;
                    *(float2*)&dst[(((bb*NH + hh)*NSEQ) + nn)*DH + dd] = v;
                } else {
                    *(float2*)&C[r*Ncols + cc] = v;
                }
            }
        }
    }
}

// ---------------- flash attention (tf32 mma) ----------------
// Block: 64 queries x full key sweep (tiles of 64). 4 warps, warp = 16 rows.
// STAGE1: p = sigmoid(s * mask), no normalization.
// STAGE2: online softmax of s*SCALE (SCALE folded into Q).
template<bool STAGE1>
__global__ __launch_bounds__(128) void attn_tf32(
    const float* __restrict__ Q, const float* __restrict__ K,
    const float* __restrict__ V, const float* __restrict__ mask,
    float* __restrict__ out)
{
    __shared__ uint32_t KPs[64][68];   // Q staging -> K tile -> P tile (pad 68: CF)
    __shared__ uint32_t Vs[64][72];    // V tile (pad 72: CF for PV B-frags)

    const int tid = threadIdx.x, warp = tid >> 5, lane = tid & 31;
    const int lr = lane >> 2, lc = lane & 3;
    const int bh = blockIdx.x, qt = blockIdx.y;
    const int b = bh >> 3, h = bh & 7;

    // ---- stage Q tile (with SCALE folded in for stage 2) ----
    const float* Qbase = Q + (bh*NSEQ + qt*64)*DH;
    for (int i = tid; i < 1024; i += 128) {
        float4 v = *(const float4*)(Qbase + i*4);
        if (!STAGE1) { v.x *= SCALE; v.y *= SCALE; v.z *= SCALE; v.w *= SCALE; }
        const int row = i >> 4, col = (i & 15) * 4;
        *(uint4*)&KPs[row][col] = make_uint4(f2tf(v.x), f2tf(v.y), f2tf(v.z), f2tf(v.w));
    }
    __syncthreads();

    uint32_t qf[8][4];
    {
        const int r = warp*16 + lr;
        #pragma unroll
        for (int ks = 0; ks < 8; ks++) {
            const int k0 = ks*8 + lc;
            qf[ks][0] = KPs[r][k0];    qf[ks][1] = KPs[r+8][k0];
            qf[ks][2] = KPs[r][k0+4];  qf[ks][3] = KPs[r+8][k0+4];
        }
    }

    float o[8][4];
    #pragma unroll
    for (int nt = 0; nt < 8; nt++)
        #pragma unroll
        for (int u = 0; u < 4; u++) o[nt][u] = 0.f;
    float mrow[2] = {-1e30f, -1e30f}, lrow[2] = {0.f, 0.f};

    const float* Kbase = K + bh*NSEQ*DH;
    const float* Vbase = V + bh*NSEQ*DH;

    for (int t = 0; t < NSEQ/64; t++) {
        __syncthreads();   // prior PV done before overwriting tiles
        for (int i = tid; i < 1024; i += 128) {
            const int row = i >> 4, col = (i & 15) * 4;
            float4 kv = *(const float4*)(Kbase + t*4096 + i*4);
            *(uint4*)&KPs[row][col] = make_uint4(f2tf(kv.x), f2tf(kv.y), f2tf(kv.z), f2tf(kv.w));
            float4 vv = *(const float4*)(Vbase + t*4096 + i*4);
            *(uint4*)&Vs[row][col]  = make_uint4(f2tf(vv.x), f2tf(vv.y), f2tf(vv.z), f2tf(vv.w));
        }
        __syncthreads();

        // ---- S = Q @ K^T (64 mma / warp) ----
        float s[8][4];
        #pragma unroll
        for (int nt = 0; nt < 8; nt++)
            #pragma unroll
            for (int u = 0; u < 4; u++) s[nt][u] = 0.f;
        #pragma unroll
        for (int ks = 0; ks < 8; ks++) {
            const int kk = ks*8 + lc;
            uint32_t bf[8][2];
            #pragma unroll
            for (int nt = 0; nt < 8; nt++) {
                const int n = nt*8 + lr;
                bf[nt][0] = KPs[n][kk];
                bf[nt][1] = KPs[n][kk+4];
            }
            #pragma unroll
            for (int nt = 0; nt < 8; nt++)
                mma8(s[nt], qf[ks], bf[nt]);
        }
        __syncthreads();   // all warps done reading K before P overwrites it

        // ---- elementwise: sigmoid / online softmax; write P into KPs ----
        const int prow = warp*16 + lr;
        if (STAGE1) {
            const int qrow0 = qt*64 + prow;
            #pragma unroll
            for (int nt = 0; nt < 8; nt++) {
                const int ccol = t*64 + nt*8 + 2*lc;
                #pragma unroll
                for (int h2 = 0; h2 < 2; h2++) {
                    float2 mv = *(const float2*)(mask + (qrow0 + h2*8)*NSEQ + ccol);
                    const float p0 = 1.f / (1.f + __expf(-s[nt][h2*2]   * mv.x));
                    const float p1 = 1.f / (1.f + __expf(-s[nt][h2*2+1] * mv.y));
                    KPs[prow + h2*8][nt*8 + 2*lc]     = f2tf(p0);
                    KPs[prow + h2*8][nt*8 + 2*lc + 1] = f2tf(p1);
                }
            }
        } else {
            #pragma unroll
            for (int h2 = 0; h2 < 2; h2++) {
                float tmax = -1e30f;
                #pragma unroll
                for (int nt = 0; nt < 8; nt++)
                    tmax = fmaxf(tmax, fmaxf(s[nt][h2*2], s[nt][h2*2+1]));
                tmax = fmaxf(tmax, __shfl_xor_sync(0xffffffffu, tmax, 1));
                tmax = fmaxf(tmax, __shfl_xor_sync(0xffffffffu, tmax, 2));
                const float mnew  = fmaxf(mrow[h2], tmax);
                const float alpha = __expf(mrow[h2] - mnew);
                mrow[h2] = mnew;
                float rsum = 0.f;
                #pragma unroll
                for (int nt = 0; nt < 8; nt++) {
                    const float p0 = __expf(s[nt][h2*2]   - mnew);
                    const float p1 = __expf(s[nt][h2*2+1] - mnew);
                    rsum += p0 + p1;
                    KPs[prow + h2*8][nt*8 + 2*lc]     = f2tf(p0);
                    KPs[prow + h2*8][nt*8 + 2*lc + 1] = f2tf(p1);
                    o[nt][h2*2]   *= alpha;
                    o[nt][h2*2+1] *= alpha;
                }
                rsum += __shfl_xor_sync(0xffffffffu, rsum, 1);
                rsum += __shfl_xor_sync(0xffffffffu, rsum, 2);
                lrow[h2] = lrow[h2]*alpha + rsum;
            }
        }
        __syncthreads();   // P visible to all warps

        // ---- O += P @ V (64 mma / warp) ----
        #pragma unroll
        for (int ks = 0; ks < 8; ks++) {
            const int r = warp*16 + lr, k0 = ks*8 + lc;
            uint32_t pa[4] = { KPs[r][k0], KPs[r+8][k0], KPs[r][k0+4], KPs[r+8][k0+4] };
            #pragma unroll
            for (int nt = 0; nt < 8; nt++) {
                uint32_t bv[2] = { Vs[k0][nt*8 + lr], Vs[k0+4][nt*8 + lr] };
                mma8(o[nt], pa, bv);
            }
        }
    }

    // ---- epilogue ----
    float* obase = out + b*NSEQ*DIM + h*DH;
    #pragma unroll
    for (int h2 = 0; h2 < 2; h2++) {
        const float inv = STAGE1 ? 1.f : (1.f / lrow[h2]);
        const int n = qt*64 + warp*16 + lr + h2*8;
        #pragma unroll
        for (int nt = 0; nt < 8; nt++) {
            float2 v = make_float2(o[nt][h2*2]*inv, o[nt][h2*2+1]*inv);
            *(float2*)(obase + n*DIM + nt*8 + 2*lc) = v;
        }
    }
}

// ---------------- launch ----------------
extern "C" void kernel_launch(void* const* d_in, const int* in_sizes, int n_in,
                              void* d_out, int out_size)
{
    const float* x     = (const float*)d_in[0];
    const float* mask  = (const float*)d_in[1];
    const float* Wqkv1 = (const float*)d_in[2];
    const float* bqkv1 = (const float*)d_in[3];
    const float* Wqkv2 = (const float*)d_in[4];
    const float* bqkv2 = (const float*)d_in[5];
    const float* Wnn1  = (const float*)d_in[6];
    const float* bnn1  = (const float*)d_in[7];
    float* out = (float*)d_out;

    float *q1, *k1, *v1, *o1, *q2, *k2, *v2, *att;
    cudaGetSymbolAddress((void**)&q1, g_q1);
    cudaGetSymbolAddress((void**)&k1, g_k1);
    cudaGetSymbolAddress((void**)&v1, g_v1);
    cudaGetSymbolAddress((void**)&o1, g_o1);
    cudaGetSymbolAddress((void**)&q2, g_q2);
    cudaGetSymbolAddress((void**)&k2, g_k2);
    cudaGetSymbolAddress((void**)&v2, g_v2);
    cudaGetSymbolAddress((void**)&att, g_att);

    const int M = BATCH * NSEQ;   // 8192

    dim3 gridQKV(3*DIM/128, M/128);   // 12 x 64
    dim3 gridOut(DIM/128, M/128);     // 4 x 64
    dim3 gridAtt(BH, NSEQ/64);        // 64 x 16

    gemm_tf32<1><<<gridQKV, 256>>>(x, Wqkv1, bqkv1, nullptr, q1, k1, v1, 3*DIM);
    attn_tf32<true><<<gridAtt, 128>>>(q1, k1, v1, mask, o1);
    gemm_tf32<1><<<gridQKV, 256>>>(o1, Wqkv2, bqkv2, nullptr, q2, k2, v2, 3*DIM);
    attn_tf32<false><<<gridAtt, 128>>>(q2, k2, v2, nullptr, att);
    gemm_tf32<0><<<gridOut, 256>>>(att, Wnn1, bnn1, out, nullptr, nullptr, nullptr, DIM);
}

// round 3
// speedup vs baseline: 3.5665x; 1.2015x over previous
#include <cuda_runtime.h>
#include <cstdint>

#define BATCH 8
#define NSEQ  1024
#define DIM   512
#define NH    8
#define DH    64
#define BH    64
#define SCALE 0.044194173824159216f   // 512^-0.5

// ---------------- scratch (device globals: alloc-guard safe) ----------------
__device__ float g_q1[BH*NSEQ*DH];
__device__ float g_k1[BH*NSEQ*DH];
__device__ float g_v1[BH*NSEQ*DH];
__device__ float g_o1[BATCH*NSEQ*DIM];
__device__ float g_q2[BH*NSEQ*DH];
__device__ float g_k2[BH*NSEQ*DH];
__device__ float g_v2[BH*NSEQ*DH];
__device__ float g_att[BATCH*NSEQ*DIM];
__device__ float g_xc[BATCH*NSEQ*DIM];     // tf32-rounded x
__device__ float g_w1[DIM*3*DIM];          // tf32-rounded weights
__device__ float g_w2[DIM*3*DIM];
__device__ float g_wn[DIM*DIM];

// ---------------- helpers ----------------
__device__ __forceinline__ uint32_t f2tf(float x) {
    uint32_t r;
    asm("cvt.rna.tf32.f32 %0, %1;" : "=r"(r) : "f"(x));
    return r;
}
__device__ __forceinline__ float u2f(uint32_t u) { return __uint_as_float(u); }

__device__ __forceinline__ void mma8(float* c, const uint32_t* a, const uint32_t* b) {
    asm volatile(
        "mma.sync.aligned.m16n8k8.row.col.f32.tf32.tf32.f32 "
        "{%0,%1,%2,%3}, {%4,%5,%6,%7}, {%8,%9}, {%0,%1,%2,%3};\n"
        : "+f"(c[0]), "+f"(c[1]), "+f"(c[2]), "+f"(c[3])
        : "r"(a[0]), "r"(a[1]), "r"(a[2]), "r"(a[3]), "r"(b[0]), "r"(b[1]));
}
__device__ __forceinline__ void ldsm4(uint32_t& r0, uint32_t& r1, uint32_t& r2, uint32_t& r3,
                                      uint32_t addr) {
    asm volatile("ldmatrix.sync.aligned.m8n8.x4.shared.b16 {%0,%1,%2,%3}, [%4];"
        : "=r"(r0), "=r"(r1), "=r"(r2), "=r"(r3) : "r"(addr));
}
__device__ __forceinline__ void cpa16(uint32_t dst, const void* src) {
    asm volatile("cp.async.cg.shared.global [%0], [%1], 16;" :: "r"(dst), "l"(src));
}
#define CP_COMMIT()  asm volatile("cp.async.commit_group;")
#define CP_WAIT(n)   asm volatile("cp.async.wait_group " #n ";")

// ---------------- tf32 pre-convert pass ----------------
__global__ void cvt_tf32(const float4* __restrict__ src, float4* __restrict__ dst, int n4) {
    int i = blockIdx.x * 256 + threadIdx.x;
    if (i < n4) {
        float4 v = src[i];
        dst[i] = make_float4(u2f(f2tf(v.x)), u2f(f2tf(v.y)), u2f(f2tf(v.z)), u2f(f2tf(v.w)));
    }
}

// ---------------- GEMM: C[M,Nc] = A[M,512] @ W[512,Nc] + bias ----------------
// Block 128x128, 8 warps, warp 32x64, K chunk 32. cp.async double-buffered.
// A and W must already be tf32-in-f32. QKV=1 scatters into q/k/v [B,H,N,D] with f2tf.
template<int QKV>
__global__ __launch_bounds__(256) void gemm_tf32(
    const float* __restrict__ A, const float* __restrict__ W,
    const float* __restrict__ bias, float* __restrict__ C,
    float* __restrict__ Qo, float* __restrict__ Ko, float* __restrict__ Vo,
    int Ncols, float qscale)
{
    extern __shared__ uint32_t sm[];
    // per-buf: As[128][36] = 4608 w, Bs[32][136] = 4352 w -> 8960 w; two bufs.
    const int tid = threadIdx.x, warp = tid >> 5, lane = tid & 31;
    const int wm = warp & 3, wn = warp >> 2, lr = lane >> 2, lc = lane & 3;
    const int row0 = blockIdx.y * 128, col0 = blockIdx.x * 128;
    const int ar = tid >> 3, ac = (tid & 7) * 4;
    const int br = tid >> 5, bc = (tid & 31) * 4;
    const uint32_t smb = (uint32_t)__cvta_generic_to_shared(sm);

    float acc[2][8][4] = {};

    // prologue: issue k-tile 0
    {
        #pragma unroll
        for (int p = 0; p < 4; p++) {
            cpa16(smb + ((ar + 32*p)*36 + ac)*4, &A[(row0 + ar + 32*p)*DIM + ac]);
            cpa16(smb + (4608 + (br + 8*p)*136 + bc)*4, &W[(br + 8*p)*Ncols + col0 + bc]);
        }
        CP_COMMIT();
    }

    for (int i = 0; i < 16; i++) {
        const int bu = i & 1;
        if (i < 15) {
            const int nb = bu ^ 1, kt = (i+1)*32;
            #pragma unroll
            for (int p = 0; p < 4; p++) {
                cpa16(smb + (nb*8960 + (ar + 32*p)*36 + ac)*4,
                      &A[(row0 + ar + 32*p)*DIM + kt + ac]);
                cpa16(smb + (nb*8960 + 4608 + (br + 8*p)*136 + bc)*4,
                      &W[(kt + br + 8*p)*Ncols + col0 + bc]);
            }
            CP_COMMIT();
            CP_WAIT(1);
        } else {
            CP_WAIT(0);
        }
        __syncthreads();

        const uint32_t* As = sm + bu*8960;
        const uint32_t* Bs = sm + bu*8960 + 4608;
        #pragma unroll
        for (int ks = 0; ks < 4; ks++) {
            const int k0 = ks*8 + lc;
            uint32_t af[2][4], bf[8][2];
            #pragma unroll
            for (int mt = 0; mt < 2; mt++) {
                const int r = wm*32 + mt*16 + lr;
                af[mt][0] = As[r*36 + k0];       af[mt][1] = As[(r+8)*36 + k0];
                af[mt][2] = As[r*36 + k0 + 4];   af[mt][3] = As[(r+8)*36 + k0 + 4];
            }
            #pragma unroll
            for (int nt = 0; nt < 8; nt++) {
                const int n = wn*64 + nt*8 + lr;
                bf[nt][0] = Bs[k0*136 + n];
                bf[nt][1] = Bs[(k0+4)*136 + n];
            }
            #pragma unroll
            for (int mt = 0; mt < 2; mt++)
                #pragma unroll
                for (int nt = 0; nt < 8; nt++)
                    mma8(acc[mt][nt], af[mt], bf[nt]);
        }
        __syncthreads();
    }

    // epilogue
    #pragma unroll
    for (int mt = 0; mt < 2; mt++) {
        const int rbase = row0 + wm*32 + mt*16 + lr;
        #pragma unroll
        for (int nt = 0; nt < 8; nt++) {
            const int cc = col0 + wn*64 + nt*8 + 2*lc;
            const float b0 = bias[cc], b1 = bias[cc+1];
            #pragma unroll
            for (int h2 = 0; h2 < 2; h2++) {
                const int r = rbase + h2*8;
                float v0 = acc[mt][nt][h2*2]   + b0;
                float v1 = acc[mt][nt][h2*2+1] + b1;
                if (QKV) {
                    const int part = cc >> 9;
                    const int hh   = (cc >> 6) & 7;
                    const int dd   = cc & 63;
                    const int bb   = r >> 10;
                    const int nn   = r & 1023;
                    if (part == 0) { v0 *= qscale; v1 *= qscale; }
                    float* dst = (part == 0) ? Qo : (part == 1) ? Ko : Vo;
                    float2 v = make_float2(u2f(f2tf(v0)), u2f(f2tf(v1)));
                    *(float2*)&dst[(((bb*NH + hh)*NSEQ) + nn)*DH + dd] = v;
                } else {
                    *(float2*)&C[r*Ncols + cc] = make_float2(v0, v1);
                }
            }
        }
    }
}

// ---------------- flash attention (tf32 mma, cp.async pipeline) ----------------
// Block: 64 queries, 4 warps (16 rows each), 64-key tiles, double-buffered K/V.
// Inputs Q/K/V already tf32-in-f32 (Q pre-scaled by SCALE for stage 2).
// smem words: buf b at b*8960: K[64][68] (4352 w) then V[64][72] (4608 w).
template<bool STAGE1>
__global__ __launch_bounds__(128, 3) void attn_tf32(
    const float* __restrict__ Q, const float* __restrict__ K,
    const float* __restrict__ V, const float* __restrict__ mask,
    float* __restrict__ out)
{
    extern __shared__ uint32_t sm[];
    const int tid = threadIdx.x, warp = tid >> 5, lane = tid & 31;
    const int lr = lane >> 2, lc = lane & 3;
    const int bh = blockIdx.x, qt = blockIdx.y;
    const int b = bh >> 3, h = bh & 7;
    const uint32_t smb = (uint32_t)__cvta_generic_to_shared(sm);

    const float4* Qsrc = (const float4*)(Q + (bh*NSEQ + qt*64)*DH);
    const float4* Ksrc = (const float4*)(K + bh*NSEQ*DH);
    const float4* Vsrc = (const float4*)(V + bh*NSEQ*DH);

    // prologue: Q -> K region of buf1; tile 0 -> buf0
    #pragma unroll
    for (int s5 = 0; s5 < 8; s5++) {
        const int idx = tid + 128*s5;
        const int row = idx >> 4, c16 = idx & 15;
        cpa16(smb + (8960 + row*68 + c16*4)*4, Qsrc + idx);
    }
    CP_COMMIT();
    #pragma unroll
    for (int s5 = 0; s5 < 8; s5++) {
        const int idx = tid + 128*s5;
        const int row = idx >> 4, c16 = idx & 15;
        cpa16(smb + (row*68 + c16*4)*4, Ksrc + idx);
        cpa16(smb + (4352 + row*72 + c16*4)*4, Vsrc + idx);
    }
    CP_COMMIT();
    CP_WAIT(0);
    __syncthreads();

    // Q fragments via ldmatrix (A-frag layout)
    uint32_t qf[8][4];
    {
        const uint32_t qb = smb + 8960*4
            + (warp*16 + ((lane >> 3) & 1)*8 + (lane & 7))*272 + (lane >> 4)*16;
        #pragma unroll
        for (int ks = 0; ks < 8; ks++)
            ldsm4(qf[ks][0], qf[ks][1], qf[ks][2], qf[ks][3], qb + ks*32);
    }
    __syncthreads();   // Q region may now be overwritten by tile 1

    float o[8][4] = {};
    float mrow[2] = {-1e30f, -1e30f}, lrow[2] = {0.f, 0.f};

    const uint32_t kfoff = (lane & 7)*272 + (lane >> 3)*16;   // B-frag ldmatrix offset
    const unsigned p0l = (lane & 28) | (lc >> 1);             // P shuffle src lanes
    const unsigned p1l = p0l | 2;

    for (int t = 0; t < 16; t++) {
        const int bu = t & 1;
        if (t < 15) {
            const int nb = bu ^ 1;
            #pragma unroll
            for (int s5 = 0; s5 < 8; s5++) {
                const int idx = tid + 128*s5;
                const int row = idx >> 4, c16 = idx & 15;
                cpa16(smb + (nb*8960 + row*68 + c16*4)*4,        Ksrc + (t+1)*1024 + idx);
                cpa16(smb + (nb*8960 + 4352 + row*72 + c16*4)*4, Vsrc + (t+1)*1024 + idx);
            }
            CP_COMMIT();
            CP_WAIT(1);
        } else {
            CP_WAIT(0);
        }
        __syncthreads();

        // ---- S = Q @ K^T : K B-frags via ldmatrix ----
        float s[8][4];
        #pragma unroll
        for (int nt = 0; nt < 8; nt++)
            #pragma unroll
            for (int u = 0; u < 4; u++) s[nt][u] = 0.f;

        const uint32_t kb = smb + bu*35840 + kfoff;
        #pragma unroll
        for (int nt = 0; nt < 8; nt++) {
            #pragma unroll
            for (int kg = 0; kg < 4; kg++) {
                uint32_t b0, b1, b2, b3;
                ldsm4(b0, b1, b2, b3, kb + nt*2176 + kg*64);
                uint32_t bfa[2] = {b0, b1};
                mma8(s[nt], qf[2*kg],   bfa);
                uint32_t bfb[2] = {b2, b3};
                mma8(s[nt], qf[2*kg+1], bfb);
            }
        }

        // ---- elementwise (p written back into s) ----
        if (STAGE1) {
            const int qrow0 = qt*64 + warp*16 + lr;
            #pragma unroll
            for (int nt = 0; nt < 8; nt++) {
                const int ccol = t*64 + nt*8 + 2*lc;
                float2 m0v = *(const float2*)(mask + qrow0*NSEQ + ccol);
                float2 m1v = *(const float2*)(mask + (qrow0+8)*NSEQ + ccol);
                s[nt][0] = 1.f / (1.f + __expf(-s[nt][0]*m0v.x));
                s[nt][1] = 1.f / (1.f + __expf(-s[nt][1]*m0v.y));
                s[nt][2] = 1.f / (1.f + __expf(-s[nt][2]*m1v.x));
                s[nt][3] = 1.f / (1.f + __expf(-s[nt][3]*m1v.y));
            }
        } else {
            #pragma unroll
            for (int h2 = 0; h2 < 2; h2++) {
                float tmax = -1e30f;
                #pragma unroll
                for (int nt = 0; nt < 8; nt++)
                    tmax = fmaxf(tmax, fmaxf(s[nt][h2*2], s[nt][h2*2+1]));
                tmax = fmaxf(tmax, __shfl_xor_sync(0xffffffffu, tmax, 1));
                tmax = fmaxf(tmax, __shfl_xor_sync(0xffffffffu, tmax, 2));
                const float mnew  = fmaxf(mrow[h2], tmax);
                const float alpha = __expf(mrow[h2] - mnew);
                mrow[h2] = mnew;
                float rsum = 0.f;
                #pragma unroll
                for (int nt = 0; nt < 8; nt++) {
                    const float p0 = __expf(s[nt][h2*2]   - mnew);
                    const float p1 = __expf(s[nt][h2*2+1] - mnew);
                    rsum += p0 + p1;
                    s[nt][h2*2]   = p0;
                    s[nt][h2*2+1] = p1;
                    o[nt][h2*2]   *= alpha;
                    o[nt][h2*2+1] *= alpha;
                }
                rsum += __shfl_xor_sync(0xffffffffu, rsum, 1);
                rsum += __shfl_xor_sync(0xffffffffu, rsum, 2);
                lrow[h2] = lrow[h2]*alpha + rsum;
            }
        }

        // ---- C-frag -> A-frag conversion via shuffles (P stays in regs) ----
        uint32_t pa[8][4];
        #pragma unroll
        for (int k = 0; k < 8; k++) {
            const float e0 = __shfl_sync(0xffffffffu, s[k][0], p0l);
            const float e1 = __shfl_sync(0xffffffffu, s[k][1], p0l);
            const float e2 = __shfl_sync(0xffffffffu, s[k][2], p0l);
            const float e3 = __shfl_sync(0xffffffffu, s[k][3], p0l);
            const float f0 = __shfl_sync(0xffffffffu, s[k][0], p1l);
            const float f1 = __shfl_sync(0xffffffffu, s[k][1], p1l);
            const float g2 = __shfl_sync(0xffffffffu, s[k][2], p1l);
            const float g3 = __shfl_sync(0xffffffffu, s[k][3], p1l);
            const bool odd = lc & 1;
            pa[k][0] = f2tf(odd ? e1 : e0);
            pa[k][1] = f2tf(odd ? e3 : e2);
            pa[k][2] = f2tf(odd ? f1 : f0);
            pa[k][3] = f2tf(odd ? g3 : g2);
        }

        // ---- O += P @ V (V loads scalar, conflict-free) ----
        const uint32_t* Vsp = sm + bu*8960 + 4352;
        #pragma unroll
        for (int nv = 0; nv < 8; nv++) {
            #pragma unroll
            for (int ks = 0; ks < 8; ks++) {
                uint32_t bv[2] = { Vsp[(ks*8 + lc)*72 + nv*8 + lr],
                                   Vsp[(ks*8 + 4 + lc)*72 + nv*8 + lr] };
                mma8(o[nv], pa[ks], bv);
            }
        }
        __syncthreads();
    }

    // ---- epilogue (f2tf: outputs feed the next GEMM) ----
    float* obase = out + b*NSEQ*DIM + h*DH;
    #pragma unroll
    for (int h2 = 0; h2 < 2; h2++) {
        const float inv = STAGE1 ? 1.f : (1.f / lrow[h2]);
        const int n = qt*64 + warp*16 + lr + h2*8;
        #pragma unroll
        for (int nt = 0; nt < 8; nt++) {
            float2 v = make_float2(u2f(f2tf(o[nt][h2*2]*inv)),
                                   u2f(f2tf(o[nt][h2*2+1]*inv)));
            *(float2*)(obase + n*DIM + nt*8 + 2*lc) = v;
        }
    }
}

// ---------------- launch ----------------
extern "C" void kernel_launch(void* const* d_in, const int* in_sizes, int n_in,
                              void* d_out, int out_size)
{
    const float* x     = (const float*)d_in[0];
    const float* mask  = (const float*)d_in[1];
    const float* Wqkv1 = (const float*)d_in[2];
    const float* bqkv1 = (const float*)d_in[3];
    const float* Wqkv2 = (const float*)d_in[4];
    const float* bqkv2 = (const float*)d_in[5];
    const float* Wnn1  = (const float*)d_in[6];
    const float* bnn1  = (const float*)d_in[7];
    float* out = (float*)d_out;

    float *q1, *k1, *v1, *o1, *q2, *k2, *v2, *att, *xc, *w1, *w2, *wn;
    cudaGetSymbolAddress((void**)&q1, g_q1);
    cudaGetSymbolAddress((void**)&k1, g_k1);
    cudaGetSymbolAddress((void**)&v1, g_v1);
    cudaGetSymbolAddress((void**)&o1, g_o1);
    cudaGetSymbolAddress((void**)&q2, g_q2);
    cudaGetSymbolAddress((void**)&k2, g_k2);
    cudaGetSymbolAddress((void**)&v2, g_v2);
    cudaGetSymbolAddress((void**)&att, g_att);
    cudaGetSymbolAddress((void**)&xc, g_xc);
    cudaGetSymbolAddress((void**)&w1, g_w1);
    cudaGetSymbolAddress((void**)&w2, g_w2);
    cudaGetSymbolAddress((void**)&wn, g_wn);

    const int SMEM = 71680;
    cudaFuncSetAttribute(gemm_tf32<1>, cudaFuncAttributeMaxDynamicSharedMemorySize, SMEM);
    cudaFuncSetAttribute(gemm_tf32<0>, cudaFuncAttributeMaxDynamicSharedMemorySize, SMEM);
    cudaFuncSetAttribute(attn_tf32<true>,  cudaFuncAttributeMaxDynamicSharedMemorySize, SMEM);
    cudaFuncSetAttribute(attn_tf32<false>, cudaFuncAttributeMaxDynamicSharedMemorySize, SMEM);

    const int M = BATCH * NSEQ;   // 8192

    // tf32 pre-convert: x and weights
    cvt_tf32<<<(M*DIM/4 + 255)/256, 256>>>((const float4*)x, (float4*)xc, M*DIM/4);
    cvt_tf32<<<(DIM*3*DIM/4 + 255)/256, 256>>>((const float4*)Wqkv1, (float4*)w1, DIM*3*DIM/4);
    cvt_tf32<<<(DIM*3*DIM/4 + 255)/256, 256>>>((const float4*)Wqkv2, (float4*)w2, DIM*3*DIM/4);
    cvt_tf32<<<(DIM*DIM/4 + 255)/256, 256>>>((const float4*)Wnn1, (float4*)wn, DIM*DIM/4);

    dim3 gridQKV(3*DIM/128, M/128);   // 12 x 64
    dim3 gridOut(DIM/128, M/128);     // 4 x 64
    dim3 gridAtt(BH, NSEQ/64);        // 64 x 16

    gemm_tf32<1><<<gridQKV, 256, SMEM>>>(xc, w1, bqkv1, nullptr, q1, k1, v1, 3*DIM, 1.f);
    attn_tf32<true><<<gridAtt, 128, SMEM>>>(q1, k1, v1, mask, o1);
    gemm_tf32<1><<<gridQKV, 256, SMEM>>>(o1, w2, bqkv2, nullptr, q2, k2, v2, 3*DIM, SCALE);
    attn_tf32<false><<<gridAtt, 128, SMEM>>>(q2, k2, v2, nullptr, att);
    gemm_tf32<0><<<gridOut, 256, SMEM>>>(att, wn, bnn1, out, nullptr, nullptr, nullptr, DIM, 1.f);
}